// round 5
// baseline (speedup 1.0000x reference)
#include <cuda_runtime.h>
#include <cuda_fp16.h>
#include <cstdint>

// ============================================================================
// GCN layer: out = relu(diag(d) A diag(d) X W + b), d = rsqrt(rowsum(A))
// R4: big GEMM switched tf32 -> f16 HMMA m16n8k16 (2x FLOP/instr).
//   d = rsqrt(rowsum A)                      (kernel 1)
//   Zt_h[n,k] = f16( d_k * (X@W)[k,n] )      (kernel 2)
//   part = A_f16 @ Zt_h^T   (K-split=2)      (kernel 3, A converted in-kernel)
//   out = relu(d_m*(p0+p1) + b)              (kernel 4)
// ============================================================================

#define NROWS 8192
#define FDIM  128
#define ODIM  128

__device__ __align__(128) float  g_d[NROWS];
__device__ __align__(128) __half g_Zth[ODIM * NROWS];               // [n][k] f16
__device__ __align__(128) float  g_part[2 * (size_t)NROWS * ODIM];  // K-split partials

// ---------------------------------------------------------------------------
__device__ __forceinline__ uint32_t smem_u32(const void* p) {
    uint32_t a;
    asm("{ .reg .u64 t; cvta.to.shared.u64 t, %1; cvt.u32.u64 %0, t; }"
        : "=r"(a) : "l"(p));
    return a;
}

#define CPA16(dst, src) \
    asm volatile("cp.async.cg.shared.global [%0], [%1], 16;" :: "r"(dst), "l"(src) : "memory")
#define CPA_COMMIT() asm volatile("cp.async.commit_group;" ::: "memory")
#define CPA_WAIT(n)  asm volatile("cp.async.wait_group %0;" :: "n"(n) : "memory")

__device__ __forceinline__ void mma_f16(float* c, const uint32_t* a, const uint32_t* b) {
    asm volatile(
        "mma.sync.aligned.m16n8k16.row.col.f32.f16.f16.f32 "
        "{%0,%1,%2,%3}, {%4,%5,%6,%7}, {%8,%9}, {%0,%1,%2,%3};"
        : "+f"(c[0]), "+f"(c[1]), "+f"(c[2]), "+f"(c[3])
        : "r"(a[0]), "r"(a[1]), "r"(a[2]), "r"(a[3]), "r"(b[0]), "r"(b[1]));
}

// ---------------------------------------------------------------------------
// Kernel 1: d[r] = rsqrt(sum_k A[r,k])
// ---------------------------------------------------------------------------
__global__ __launch_bounds__(256) void rowsum_kernel(const float* __restrict__ A) {
    int row = blockIdx.x;
    const float4* p = reinterpret_cast<const float4*>(A + (size_t)row * NROWS);
    float s = 0.f;
#pragma unroll
    for (int i = 0; i < 8; ++i) {
        float4 v = p[threadIdx.x + i * 256];
        s += (v.x + v.y) + (v.z + v.w);
    }
#pragma unroll
    for (int o = 16; o; o >>= 1) s += __shfl_xor_sync(0xffffffffu, s, o);
    __shared__ float ws[8];
    if ((threadIdx.x & 31) == 0) ws[threadIdx.x >> 5] = s;
    __syncthreads();
    if (threadIdx.x < 8) {
        float t = ws[threadIdx.x];
        t += __shfl_xor_sync(0xffu, t, 4);
        t += __shfl_xor_sync(0xffu, t, 2);
        t += __shfl_xor_sync(0xffu, t, 1);
        if (threadIdx.x == 0) g_d[row] = rsqrtf(t);
    }
}

// ---------------------------------------------------------------------------
// Kernel 2: Zt_h[n,k] = f16_rn( d[k] * sum_f X[k,f] W[f,n] )
// ---------------------------------------------------------------------------
__global__ __launch_bounds__(256) void xw_kernel(const float* __restrict__ X,
                                                 const float* __restrict__ W) {
    __shared__ float Ws[128 * 64];
    __shared__ float Xs[16 * 128];
    int tid = threadIdx.x;
    int n0 = blockIdx.y * 64;
    int k0 = blockIdx.x * 16;
    for (int i = tid; i < 128 * 64; i += 256) {
        int f = i >> 6, nl = i & 63;
        Ws[i] = W[f * ODIM + n0 + nl];
    }
    for (int i = tid; i < 16 * 128; i += 256)
        Xs[i] = X[(size_t)(k0 + (i >> 7)) * FDIM + (i & 127)];
    __syncthreads();

    int nl = tid & 63, ks = tid >> 6;
    for (int kk = ks; kk < 16; kk += 4) {
        float acc = 0.f;
#pragma unroll 8
        for (int f = 0; f < 128; ++f) acc += Xs[kk * 128 + f] * Ws[f * 64 + nl];
        int k = k0 + kk;
        g_Zth[(size_t)(n0 + nl) * NROWS + k] = __float2half_rn(g_d[k] * acc);
    }
}

// ---------------------------------------------------------------------------
// Kernel 3: f16 GEMM. grid (64, 2), 256 thr (8 warps, warp tile 64x32).
// CTA tile 128x128, k-tile 32. A: LDG f32 -> cvt f16 -> STS (reg-pipelined).
// B: cp.async f16 from g_Zth. Smem rows padded to 80B (conflict-free frags).
// ---------------------------------------------------------------------------
static constexpr int KT       = 32;
static constexpr int KC       = NROWS / 2;     // 4096 per K-split
static constexpr int NKT      = KC / KT;       // 128
static constexpr int ROW_B    = 80;            // padded row bytes (32 f16 + 16B pad)
static constexpr int TILE_B   = 128 * ROW_B;   // 10240 B per tile
static constexpr int RING     = 3;
static constexpr int DYN_SMEM = 2 * RING * TILE_B;  // A_h ring + B ring = 61440

__device__ __forceinline__ void ldgA(const float* __restrict__ A, int m0, int kbase,
                                     int t, int tid, float4* R) {
    int row = tid >> 1, p = tid & 1;
    const float4* src = reinterpret_cast<const float4*>(
        A + (size_t)(m0 + row) * NROWS + kbase + t * KT + p * 16);
#pragma unroll
    for (int i = 0; i < 4; ++i) R[i] = src[i];
}

__device__ __forceinline__ void cvtSTS(char* Ah, int tid, const float4* R) {
    int row = tid >> 1, p = tid & 1;
    char* dst = Ah + row * ROW_B + p * 32;
#pragma unroll
    for (int i = 0; i < 4; ++i) {
        __half2 h0 = __floats2half2_rn(R[i].x, R[i].y);
        __half2 h1 = __floats2half2_rn(R[i].z, R[i].w);
        uint2 u;
        u.x = *reinterpret_cast<uint32_t*>(&h0);
        u.y = *reinterpret_cast<uint32_t*>(&h1);
        *reinterpret_cast<uint2*>(dst + i * 8) = u;
    }
}

__device__ __forceinline__ void cpaB(uint32_t Bb, int kbase, int t, int tid) {
    int k0 = kbase + t * KT;
#pragma unroll
    for (int rep = 0; rep < 2; ++rep) {
        int c = tid + rep * 256;          // 0..511
        int row = c >> 2, seg = c & 3;
        const __half* src = g_Zth + (size_t)row * NROWS + k0 + seg * 8;
        CPA16(Bb + (uint32_t)(row * ROW_B + seg * 16), src);
    }
}

__global__ __launch_bounds__(256, 1) void gemm_kernel(const float* __restrict__ A) {
    extern __shared__ __align__(16) char sm[];
    char* AhBase = sm;
    char* BBase  = sm + RING * TILE_B;
    uint32_t Bu = smem_u32(BBase);

    int tid = threadIdx.x, wid = tid >> 5, lane = tid & 31;
    int m0 = blockIdx.x * 128;
    int kbase = blockIdx.y * KC;
    int mw = (wid >> 2) * 64, nw = (wid & 3) * 32;
    int r = lane >> 2, q = lane & 3;

    float acc[4][4][4];
#pragma unroll
    for (int i = 0; i < 4; ++i)
#pragma unroll
        for (int j = 0; j < 4; ++j)
#pragma unroll
            for (int v = 0; v < 4; ++v) acc[i][j][v] = 0.f;

    float4 R[4];

    // prologue
    ldgA(A, m0, kbase, 0, tid, R);
    cpaB(Bu, kbase, 0, tid); CPA_COMMIT();
    cpaB(Bu + TILE_B, kbase, 1, tid); CPA_COMMIT();
    cvtSTS(AhBase, tid, R);               // A tile 0 -> slot 0
    ldgA(A, m0, kbase, 1, tid, R);        // A tile 1 in regs
    CPA_WAIT(1);                          // B(0) arrived
    __syncthreads();

    for (int t = 0; t < NKT; ++t) {
        if (t + 2 < NKT) cpaB(Bu + ((t + 2) % RING) * TILE_B, kbase, t + 2, tid);
        CPA_COMMIT();

        const char* Ab = AhBase + (t % RING) * TILE_B;
        const char* Bb = BBase + (t % RING) * TILE_B;
#pragma unroll
        for (int ks = 0; ks < 2; ++ks) {
            int kb2 = (ks * 16 + 2 * q) * 2;   // byte offset within row
            uint32_t a[4][4], b[4][2];
#pragma unroll
            for (int i = 0; i < 4; ++i) {
                const char* pa = Ab + (mw + i * 16 + r) * ROW_B + kb2;
                a[i][0] = *reinterpret_cast<const uint32_t*>(pa);
                a[i][1] = *reinterpret_cast<const uint32_t*>(pa + 8 * ROW_B);
                a[i][2] = *reinterpret_cast<const uint32_t*>(pa + 16);
                a[i][3] = *reinterpret_cast<const uint32_t*>(pa + 8 * ROW_B + 16);
            }
#pragma unroll
            for (int j = 0; j < 4; ++j) {
                const char* pb = Bb + (nw + j * 8 + r) * ROW_B + kb2;
                b[j][0] = *reinterpret_cast<const uint32_t*>(pb);
                b[j][1] = *reinterpret_cast<const uint32_t*>(pb + 16);
            }
#pragma unroll
            for (int i = 0; i < 4; ++i)
#pragma unroll
                for (int j = 0; j < 4; ++j)
                    mma_f16(acc[i][j], a[i], b[j]);
        }

        if (t + 1 < NKT) cvtSTS(AhBase + ((t + 1) % RING) * TILE_B, tid, R);
        if (t + 2 < NKT) ldgA(A, m0, kbase, t + 2, tid, R);
        CPA_WAIT(1);                      // B(t+1) arrived
        __syncthreads();
    }

    // write K-split partials
    float* P = g_part + (size_t)blockIdx.y * NROWS * ODIM;
#pragma unroll
    for (int i = 0; i < 4; ++i) {
        int row0 = m0 + mw + i * 16 + r;
#pragma unroll
        for (int j = 0; j < 4; ++j) {
            int col = nw + j * 8 + 2 * q;
            *reinterpret_cast<float2*>(&P[(size_t)row0 * ODIM + col]) =
                make_float2(acc[i][j][0], acc[i][j][1]);
            *reinterpret_cast<float2*>(&P[(size_t)(row0 + 8) * ODIM + col]) =
                make_float2(acc[i][j][2], acc[i][j][3]);
        }
    }
}

// ---------------------------------------------------------------------------
// Kernel 4: out = relu(d_m * (p0 + p1) + b_n)
// ---------------------------------------------------------------------------
__global__ __launch_bounds__(256) void combine_kernel(const float* __restrict__ bias,
                                                      float* __restrict__ out) {
    int i = blockIdx.x * 256 + threadIdx.x;
    const float4* P0 = reinterpret_cast<const float4*>(g_part);
    const float4* P1 = P0 + (size_t)NROWS * ODIM / 4;
    int m = i >> 5;
    int c = (i & 31) * 4;
    float4 p0 = P0[i], p1 = P1[i];
    float4 bb = *reinterpret_cast<const float4*>(bias + c);
    float dv = g_d[m];
    float4 o;
    o.x = fmaxf(fmaf(dv, p0.x + p1.x, bb.x), 0.f);
    o.y = fmaxf(fmaf(dv, p0.y + p1.y, bb.y), 0.f);
    o.z = fmaxf(fmaf(dv, p0.z + p1.z, bb.z), 0.f);
    o.w = fmaxf(fmaf(dv, p0.w + p1.w, bb.w), 0.f);
    reinterpret_cast<float4*>(out)[i] = o;
}

// ---------------------------------------------------------------------------
extern "C" void kernel_launch(void* const* d_in, const int* in_sizes, int n_in,
                              void* d_out, int out_size) {
    const float* A = (const float*)d_in[0];
    const float* X = (const float*)d_in[1];
    const float* W = (const float*)d_in[2];
    const float* b = (const float*)d_in[3];
    float* out = (float*)d_out;
    (void)in_sizes; (void)n_in; (void)out_size;

    rowsum_kernel<<<NROWS, 256>>>(A);
    dim3 g2(NROWS / 16, 2);
    xw_kernel<<<g2, 256>>>(X, W);
    cudaFuncSetAttribute(gemm_kernel,
                         cudaFuncAttributeMaxDynamicSharedMemorySize, DYN_SMEM);
    dim3 g3(NROWS / 128, 2);
    gemm_kernel<<<g3, 256, DYN_SMEM>>>(A);
    combine_kernel<<<NROWS * ODIM / 4 / 256, 256>>>(b, out);
}

// round 8
// speedup vs baseline: 1.1122x; 1.1122x over previous
#include <cuda_runtime.h>
#include <cuda_fp16.h>
#include <cstdint>

// ============================================================================
// GCN layer: out = relu(diag(d) A diag(d) X W + b), d = rsqrt(rowsum(A))
// R5: rowsum fused with A->f16 conversion (g_Ah); GEMM is a pure cp.async
//     4-stage pipeline (KT=64) with register-double-buffered fragments.
//   k1: d = rsqrt(rowsum A); A_h = f16(A)
//   k2: Zt_h[n,k] = f16( d_k * (X@W)[k,n] )
//   k3: part = A_h @ Zt_h^T  (f16 HMMA m16n8k16, K-split=2)
//   k4: out = relu(d_m*(p0+p1) + b)
// ============================================================================

#define NROWS 8192
#define FDIM  128
#define ODIM  128

__device__ __align__(128) float  g_d[NROWS];
__device__ __align__(128) __half g_Ah[(size_t)NROWS * NROWS];       // f16(A), 128MB
__device__ __align__(128) __half g_Zth[ODIM * NROWS];               // [n][k] f16
__device__ __align__(128) float  g_part[2 * (size_t)NROWS * ODIM];  // K-split partials

// ---------------------------------------------------------------------------
__device__ __forceinline__ uint32_t smem_u32(const void* p) {
    uint32_t a;
    asm("{ .reg .u64 t; cvta.to.shared.u64 t, %1; cvt.u32.u64 %0, t; }"
        : "=r"(a) : "l"(p));
    return a;
}

#define CPA16(dst, src) \
    asm volatile("cp.async.cg.shared.global [%0], [%1], 16;" :: "r"(dst), "l"(src) : "memory")
#define CPA_COMMIT() asm volatile("cp.async.commit_group;" ::: "memory")
#define CPA_WAIT(n)  asm volatile("cp.async.wait_group %0;" :: "n"(n) : "memory")

__device__ __forceinline__ void mma_f16(float* c, const uint32_t* a, const uint32_t* b) {
    asm volatile(
        "mma.sync.aligned.m16n8k16.row.col.f32.f16.f16.f32 "
        "{%0,%1,%2,%3}, {%4,%5,%6,%7}, {%8,%9}, {%0,%1,%2,%3};"
        : "+f"(c[0]), "+f"(c[1]), "+f"(c[2]), "+f"(c[3])
        : "r"(a[0]), "r"(a[1]), "r"(a[2]), "r"(a[3]), "r"(b[0]), "r"(b[1]));
}

// ---------------------------------------------------------------------------
// Kernel 1: d[r] = rsqrt(sum_k A[r,k]); g_Ah = f16(A)
// ---------------------------------------------------------------------------
__global__ __launch_bounds__(256) void rowsum_kernel(const float* __restrict__ A) {
    int row = blockIdx.x;
    const float4* p = reinterpret_cast<const float4*>(A + (size_t)row * NROWS);
    uint2* dst = reinterpret_cast<uint2*>(g_Ah + (size_t)row * NROWS);
    float s = 0.f;
#pragma unroll
    for (int i = 0; i < 8; ++i) {
        int idx = threadIdx.x + i * 256;
        float4 v = p[idx];
        s += (v.x + v.y) + (v.z + v.w);
        __half2 h0 = __floats2half2_rn(v.x, v.y);
        __half2 h1 = __floats2half2_rn(v.z, v.w);
        uint2 u;
        u.x = *reinterpret_cast<uint32_t*>(&h0);
        u.y = *reinterpret_cast<uint32_t*>(&h1);
        dst[idx] = u;
    }
#pragma unroll
    for (int o = 16; o; o >>= 1) s += __shfl_xor_sync(0xffffffffu, s, o);
    __shared__ float ws[8];
    if ((threadIdx.x & 31) == 0) ws[threadIdx.x >> 5] = s;
    __syncthreads();
    if (threadIdx.x < 8) {
        float t = ws[threadIdx.x];
        t += __shfl_xor_sync(0xffu, t, 4);
        t += __shfl_xor_sync(0xffu, t, 2);
        t += __shfl_xor_sync(0xffu, t, 1);
        if (threadIdx.x == 0) g_d[row] = rsqrtf(t);
    }
}

// ---------------------------------------------------------------------------
// Kernel 2: Zt_h[n,k] = f16_rn( d[k] * sum_f X[k,f] W[f,n] )
// ---------------------------------------------------------------------------
__global__ __launch_bounds__(256) void xw_kernel(const float* __restrict__ X,
                                                 const float* __restrict__ W) {
    __shared__ float Ws[128 * 64];
    __shared__ float Xs[16 * 128];
    int tid = threadIdx.x;
    int n0 = blockIdx.y * 64;
    int k0 = blockIdx.x * 16;
    for (int i = tid; i < 128 * 64; i += 256) {
        int f = i >> 6, nl = i & 63;
        Ws[i] = W[f * ODIM + n0 + nl];
    }
    for (int i = tid; i < 16 * 128; i += 256)
        Xs[i] = X[(size_t)(k0 + (i >> 7)) * FDIM + (i & 127)];
    __syncthreads();

    int nl = tid & 63, ks = tid >> 6;
    for (int kk = ks; kk < 16; kk += 4) {
        float acc = 0.f;
#pragma unroll 8
        for (int f = 0; f < 128; ++f) acc += Xs[kk * 128 + f] * Ws[f * 64 + nl];
        int k = k0 + kk;
        g_Zth[(size_t)(n0 + nl) * NROWS + k] = __float2half_rn(g_d[k] * acc);
    }
}

// ---------------------------------------------------------------------------
// Kernel 3: f16 GEMM, pure cp.async. grid (64,2), 256 thr (8 warps, 64x32 wt).
// CTA tile 128x128, KT=64, RING=4 (3 tiles in flight). Rows padded to 144B.
// ---------------------------------------------------------------------------
static constexpr int KT       = 64;
static constexpr int KC       = NROWS / 2;       // 4096 per K-split
static constexpr int NKT      = KC / KT;         // 64
static constexpr int ROW_B    = 144;             // 128B payload + 16B pad
static constexpr int TILE_B   = 128 * ROW_B;     // 18432 B
static constexpr int RING     = 4;
static constexpr int DYN_SMEM = 2 * RING * TILE_B;  // 147456 B

__device__ __forceinline__ void ld_tile(uint32_t Au, uint32_t Bu, int slot,
                                        int t, int m0, int kbase, int tid) {
    int k0 = kbase + t * KT;
    uint32_t Ad = Au + slot * TILE_B;
    uint32_t Bd = Bu + slot * TILE_B;
#pragma unroll
    for (int rep = 0; rep < 8; ++rep) {
        int c   = tid + rep * 256;        // 0..2047
        int isB = c >> 10;
        int rc  = c & 1023;
        int row = rc >> 3, seg = rc & 7;
        const __half* src = isB
            ? (g_Zth + (size_t)row * NROWS + k0 + seg * 8)
            : (g_Ah + (size_t)(m0 + row) * NROWS + k0 + seg * 8);
        CPA16((isB ? Bd : Ad) + (uint32_t)(row * ROW_B + seg * 16), src);
    }
}

__device__ __forceinline__ void ld_frag(const char* Ab, const char* Bb,
                                        int mw, int nw, int r, int q, int ks,
                                        uint32_t a[4][4], uint32_t b[4][2]) {
    int kb2 = (ks * 16 + 2 * q) * 2;
#pragma unroll
    for (int i = 0; i < 4; ++i) {
        const char* pa = Ab + (mw + i * 16 + r) * ROW_B + kb2;
        a[i][0] = *reinterpret_cast<const uint32_t*>(pa);
        a[i][1] = *reinterpret_cast<const uint32_t*>(pa + 8 * ROW_B);
        a[i][2] = *reinterpret_cast<const uint32_t*>(pa + 16);
        a[i][3] = *reinterpret_cast<const uint32_t*>(pa + 8 * ROW_B + 16);
    }
#pragma unroll
    for (int j = 0; j < 4; ++j) {
        const char* pb = Bb + (nw + j * 8 + r) * ROW_B + kb2;
        b[j][0] = *reinterpret_cast<const uint32_t*>(pb);
        b[j][1] = *reinterpret_cast<const uint32_t*>(pb + 16);
    }
}

__global__ __launch_bounds__(256, 1) void gemm_kernel() {
    extern __shared__ __align__(16) char sm[];
    char* ABase = sm;
    char* BBase = sm + RING * TILE_B;
    uint32_t Au = smem_u32(ABase);
    uint32_t Bu = smem_u32(BBase);

    int tid = threadIdx.x, wid = tid >> 5, lane = tid & 31;
    int m0 = blockIdx.x * 128;
    int kbase = blockIdx.y * KC;
    int mw = (wid >> 2) * 64, nw = (wid & 3) * 32;
    int r = lane >> 2, q = lane & 3;

    float acc[4][4][4];
#pragma unroll
    for (int i = 0; i < 4; ++i)
#pragma unroll
        for (int j = 0; j < 4; ++j)
#pragma unroll
            for (int v = 0; v < 4; ++v) acc[i][j][v] = 0.f;

    // prologue: tiles 0..2 in flight
#pragma unroll
    for (int s = 0; s < RING - 1; ++s) {
        ld_tile(Au, Bu, s, s, m0, kbase, tid);
        CPA_COMMIT();
    }
    CPA_WAIT(RING - 2);      // tile 0 complete
    __syncthreads();

    uint32_t fa[2][4][4], fb[2][4][2];

    for (int t = 0; t < NKT; ++t) {
        // issue next tile early (slot (t+3)%4 was consumed at iter t-1)
        if (t + RING - 1 < NKT)
            ld_tile(Au, Bu, (t + RING - 1) % RING, t + RING - 1, m0, kbase, tid);
        CPA_COMMIT();

        const char* Ab = ABase + (t % RING) * TILE_B;
        const char* Bb = BBase + (t % RING) * TILE_B;

        ld_frag(Ab, Bb, mw, nw, r, q, 0, fa[0], fb[0]);
#pragma unroll
        for (int ks = 0; ks < 4; ++ks) {
            int cur = ks & 1;
            if (ks < 3)
                ld_frag(Ab, Bb, mw, nw, r, q, ks + 1, fa[cur ^ 1], fb[cur ^ 1]);
#pragma unroll
            for (int i = 0; i < 4; ++i)
#pragma unroll
                for (int j = 0; j < 4; ++j)
                    mma_f16(acc[i][j], fa[cur][i], fb[cur][j]);
        }

        CPA_WAIT(RING - 2);  // next tile (t+1) complete
        __syncthreads();
    }

    // write K-split partials
    float* P = g_part + (size_t)blockIdx.y * NROWS * ODIM;
#pragma unroll
    for (int i = 0; i < 4; ++i) {
        int row0 = m0 + mw + i * 16 + r;
#pragma unroll
        for (int j = 0; j < 4; ++j) {
            int col = nw + j * 8 + 2 * q;
            *reinterpret_cast<float2*>(&P[(size_t)row0 * ODIM + col]) =
                make_float2(acc[i][j][0], acc[i][j][1]);
            *reinterpret_cast<float2*>(&P[(size_t)(row0 + 8) * ODIM + col]) =
                make_float2(acc[i][j][2], acc[i][j][3]);
        }
    }
}

// ---------------------------------------------------------------------------
// Kernel 4: out = relu(d_m*(p0+p1) + b_n). 4 float4 per thread for MLP.
// ---------------------------------------------------------------------------
__global__ __launch_bounds__(256) void combine_kernel(const float* __restrict__ bias,
                                                      float* __restrict__ out) {
    const float4* P0 = reinterpret_cast<const float4*>(g_part);
    const float4* P1 = P0 + (size_t)NROWS * ODIM / 4;
    float4* O = reinterpret_cast<float4*>(out);
    int base = blockIdx.x * 1024 + threadIdx.x;
    float4 p0[4], p1[4];
#pragma unroll
    for (int u = 0; u < 4; ++u) {
        p0[u] = P0[base + u * 256];
        p1[u] = P1[base + u * 256];
    }
#pragma unroll
    for (int u = 0; u < 4; ++u) {
        int i = base + u * 256;
        int m = i >> 5;
        int c = (i & 31) * 4;
        float4 bb = *reinterpret_cast<const float4*>(bias + c);
        float dv = g_d[m];
        float4 o;
        o.x = fmaxf(fmaf(dv, p0[u].x + p1[u].x, bb.x), 0.f);
        o.y = fmaxf(fmaf(dv, p0[u].y + p1[u].y, bb.y), 0.f);
        o.z = fmaxf(fmaf(dv, p0[u].z + p1[u].z, bb.z), 0.f);
        o.w = fmaxf(fmaf(dv, p0[u].w + p1[u].w, bb.w), 0.f);
        O[i] = o;
    }
}

// ---------------------------------------------------------------------------
extern "C" void kernel_launch(void* const* d_in, const int* in_sizes, int n_in,
                              void* d_out, int out_size) {
    const float* A = (const float*)d_in[0];
    const float* X = (const float*)d_in[1];
    const float* W = (const float*)d_in[2];
    const float* b = (const float*)d_in[3];
    float* out = (float*)d_out;
    (void)in_sizes; (void)n_in; (void)out_size;

    rowsum_kernel<<<NROWS, 256>>>(A);
    dim3 g2(NROWS / 16, 2);
    xw_kernel<<<g2, 256>>>(X, W);
    cudaFuncSetAttribute(gemm_kernel,
                         cudaFuncAttributeMaxDynamicSharedMemorySize, DYN_SMEM);
    dim3 g3(NROWS / 128, 2);
    gemm_kernel<<<g3, 256, DYN_SMEM>>>();
    combine_kernel<<<NROWS * ODIM / 4 / 1024, 256>>>(b, out);
}

// round 9
// speedup vs baseline: 1.1436x; 1.0282x over previous
#include <cuda_runtime.h>
#include <cuda_fp16.h>
#include <cstdint>

// ============================================================================
// GCN layer: out = relu(diag(d) A diag(d) X W + b), d = rsqrt(rowsum(A))
// R8: GEMM fragment loads switched to ldmatrix.x4 (conflict-free), RING=5.
//   k1: d = rsqrt(rowsum A); A_h = f16(A)
//   k2: Zt_h[n,k] = f16( d_k * (X@W)[k,n] )
//   k3: part = A_h @ Zt_h^T  (f16 HMMA m16n8k16, K-split=2)
//   k4: out = relu(d_m*(p0+p1) + b)
// ============================================================================

#define NROWS 8192
#define FDIM  128
#define ODIM  128

__device__ __align__(128) float  g_d[NROWS];
__device__ __align__(128) __half g_Ah[(size_t)NROWS * NROWS];       // f16(A), 128MB
__device__ __align__(128) __half g_Zth[ODIM * NROWS];               // [n][k] f16
__device__ __align__(128) float  g_part[2 * (size_t)NROWS * ODIM];  // K-split partials

// ---------------------------------------------------------------------------
__device__ __forceinline__ uint32_t smem_u32(const void* p) {
    uint32_t a;
    asm("{ .reg .u64 t; cvta.to.shared.u64 t, %1; cvt.u32.u64 %0, t; }"
        : "=r"(a) : "l"(p));
    return a;
}

#define CPA16(dst, src) \
    asm volatile("cp.async.cg.shared.global [%0], [%1], 16;" :: "r"(dst), "l"(src) : "memory")
#define CPA_COMMIT() asm volatile("cp.async.commit_group;" ::: "memory")
#define CPA_WAIT(n)  asm volatile("cp.async.wait_group %0;" :: "n"(n) : "memory")

__device__ __forceinline__ void mma_f16(float* c, const uint32_t* a,
                                        uint32_t b0, uint32_t b1) {
    asm volatile(
        "mma.sync.aligned.m16n8k16.row.col.f32.f16.f16.f32 "
        "{%0,%1,%2,%3}, {%4,%5,%6,%7}, {%8,%9}, {%0,%1,%2,%3};"
        : "+f"(c[0]), "+f"(c[1]), "+f"(c[2]), "+f"(c[3])
        : "r"(a[0]), "r"(a[1]), "r"(a[2]), "r"(a[3]), "r"(b0), "r"(b1));
}

__device__ __forceinline__ void ldsm_x4(uint32_t* d, uint32_t addr) {
    asm volatile("ldmatrix.sync.aligned.m8n8.x4.shared.b16 {%0,%1,%2,%3}, [%4];"
        : "=r"(d[0]), "=r"(d[1]), "=r"(d[2]), "=r"(d[3]) : "r"(addr));
}

// ---------------------------------------------------------------------------
// Kernel 1: d[r] = rsqrt(sum_k A[r,k]); g_Ah = f16(A)
// ---------------------------------------------------------------------------
__global__ __launch_bounds__(256) void rowsum_kernel(const float* __restrict__ A) {
    int row = blockIdx.x;
    const float4* p = reinterpret_cast<const float4*>(A + (size_t)row * NROWS);
    uint2* dst = reinterpret_cast<uint2*>(g_Ah + (size_t)row * NROWS);
    float s = 0.f;
#pragma unroll
    for (int i = 0; i < 8; ++i) {
        int idx = threadIdx.x + i * 256;
        float4 v = p[idx];
        s += (v.x + v.y) + (v.z + v.w);
        __half2 h0 = __floats2half2_rn(v.x, v.y);
        __half2 h1 = __floats2half2_rn(v.z, v.w);
        uint2 u;
        u.x = *reinterpret_cast<uint32_t*>(&h0);
        u.y = *reinterpret_cast<uint32_t*>(&h1);
        dst[idx] = u;
    }
#pragma unroll
    for (int o = 16; o; o >>= 1) s += __shfl_xor_sync(0xffffffffu, s, o);
    __shared__ float ws[8];
    if ((threadIdx.x & 31) == 0) ws[threadIdx.x >> 5] = s;
    __syncthreads();
    if (threadIdx.x < 8) {
        float t = ws[threadIdx.x];
        t += __shfl_xor_sync(0xffu, t, 4);
        t += __shfl_xor_sync(0xffu, t, 2);
        t += __shfl_xor_sync(0xffu, t, 1);
        if (threadIdx.x == 0) g_d[row] = rsqrtf(t);
    }
}

// ---------------------------------------------------------------------------
// Kernel 2: Zt_h[n,k] = f16_rn( d[k] * sum_f X[k,f] W[f,n] )
// ---------------------------------------------------------------------------
__global__ __launch_bounds__(256) void xw_kernel(const float* __restrict__ X,
                                                 const float* __restrict__ W) {
    __shared__ float Ws[128 * 64];
    __shared__ float Xs[16 * 128];
    int tid = threadIdx.x;
    int n0 = blockIdx.y * 64;
    int k0 = blockIdx.x * 16;
    for (int i = tid; i < 128 * 64; i += 256) {
        int f = i >> 6, nl = i & 63;
        Ws[i] = W[f * ODIM + n0 + nl];
    }
    for (int i = tid; i < 16 * 128; i += 256)
        Xs[i] = X[(size_t)(k0 + (i >> 7)) * FDIM + (i & 127)];
    __syncthreads();

    int nl = tid & 63, ks = tid >> 6;
    for (int kk = ks; kk < 16; kk += 4) {
        float acc = 0.f;
#pragma unroll 8
        for (int f = 0; f < 128; ++f) acc += Xs[kk * 128 + f] * Ws[f * 64 + nl];
        int k = k0 + kk;
        g_Zth[(size_t)(n0 + nl) * NROWS + k] = __float2half_rn(g_d[k] * acc);
    }
}

// ---------------------------------------------------------------------------
// Kernel 3: f16 GEMM. grid (64,2), 256 thr (8 warps, 64x32 warp tile).
// CTA 128x128, KT=64, RING=5 (4 tiles in flight). ldmatrix.x4 fragments.
// Rows padded to 144B: 16B-unit stride 9 => rows 0..7 hit distinct banks.
// ---------------------------------------------------------------------------
static constexpr int KT       = 64;
static constexpr int KC       = NROWS / 2;       // 4096 per K-split
static constexpr int NKT      = KC / KT;         // 64
static constexpr int ROW_B    = 144;             // 128B payload + 16B pad
static constexpr int TILE_B   = 128 * ROW_B;     // 18432 B
static constexpr int RING     = 5;
static constexpr int DYN_SMEM = 2 * RING * TILE_B;  // 184320 B

__device__ __forceinline__ void ld_tile(uint32_t Au, uint32_t Bu, int slot,
                                        int t, int m0, int kbase, int tid) {
    int k0 = kbase + t * KT;
    uint32_t Ad = Au + slot * TILE_B;
    uint32_t Bd = Bu + slot * TILE_B;
#pragma unroll
    for (int rep = 0; rep < 8; ++rep) {
        int c   = tid + rep * 256;        // 0..2047
        int isB = c >> 10;
        int rc  = c & 1023;
        int row = rc >> 3, seg = rc & 7;
        const __half* src = isB
            ? (g_Zth + (size_t)row * NROWS + k0 + seg * 8)
            : (g_Ah + (size_t)(m0 + row) * NROWS + k0 + seg * 8);
        CPA16((isB ? Bd : Ad) + (uint32_t)(row * ROW_B + seg * 16), src);
    }
}

__global__ __launch_bounds__(256, 1) void gemm_kernel() {
    extern __shared__ __align__(16) char sm[];
    uint32_t Au = smem_u32(sm);
    uint32_t Bu = Au + RING * TILE_B;

    int tid = threadIdx.x, wid = tid >> 5, lane = tid & 31;
    int m0 = blockIdx.x * 128;
    int kbase = blockIdx.y * KC;
    int mw = (wid >> 2) * 64, nw = (wid & 3) * 32;
    int r = lane >> 2, q = lane & 3;

    // ldmatrix per-lane address offsets (within a tile)
    int mi1 = (lane >> 3) & 1, mi2 = lane >> 4, rr = lane & 7;
    uint32_t aoff = (uint32_t)((mw + mi1 * 8 + rr) * ROW_B + mi2 * 16);
    uint32_t boff = (uint32_t)((nw + mi2 * 8 + rr) * ROW_B + mi1 * 16);

    float acc[4][4][4];
#pragma unroll
    for (int i = 0; i < 4; ++i)
#pragma unroll
        for (int j = 0; j < 4; ++j)
#pragma unroll
            for (int v = 0; v < 4; ++v) acc[i][j][v] = 0.f;

    // prologue: tiles 0..RING-2 in flight
#pragma unroll
    for (int s = 0; s < RING - 1; ++s) {
        ld_tile(Au, Bu, s, s, m0, kbase, tid);
        CPA_COMMIT();
    }
    CPA_WAIT(RING - 2);      // tile 0 complete
    __syncthreads();

    uint32_t fa[2][4][4], fb[2][2][4];

    for (int t = 0; t < NKT; ++t) {
        if (t + RING - 1 < NKT)
            ld_tile(Au, Bu, (t + RING - 1) % RING, t + RING - 1, m0, kbase, tid);
        CPA_COMMIT();

        uint32_t At = Au + (t % RING) * TILE_B;
        uint32_t Bt = Bu + (t % RING) * TILE_B;

        // preload ks=0 fragments
#pragma unroll
        for (int i = 0; i < 4; ++i)
            ldsm_x4(fa[0][i], At + aoff + (uint32_t)(i * 16 * ROW_B));
        ldsm_x4(fb[0][0], Bt + boff);
        ldsm_x4(fb[0][1], Bt + boff + (uint32_t)(16 * ROW_B));

#pragma unroll
        for (int ks = 0; ks < 4; ++ks) {
            int cur = ks & 1;
            if (ks < 3) {
                uint32_t ko = (uint32_t)((ks + 1) * 32);
#pragma unroll
                for (int i = 0; i < 4; ++i)
                    ldsm_x4(fa[cur ^ 1][i], At + aoff + ko + (uint32_t)(i * 16 * ROW_B));
                ldsm_x4(fb[cur ^ 1][0], Bt + boff + ko);
                ldsm_x4(fb[cur ^ 1][1], Bt + boff + ko + (uint32_t)(16 * ROW_B));
            }
#pragma unroll
            for (int i = 0; i < 4; ++i) {
                mma_f16(acc[i][0], fa[cur][i], fb[cur][0][0], fb[cur][0][1]);
                mma_f16(acc[i][1], fa[cur][i], fb[cur][0][2], fb[cur][0][3]);
                mma_f16(acc[i][2], fa[cur][i], fb[cur][1][0], fb[cur][1][1]);
                mma_f16(acc[i][3], fa[cur][i], fb[cur][1][2], fb[cur][1][3]);
            }
        }

        CPA_WAIT(RING - 2);  // next tile (t+1) complete
        __syncthreads();
    }

    // write K-split partials
    float* P = g_part + (size_t)blockIdx.y * NROWS * ODIM;
#pragma unroll
    for (int i = 0; i < 4; ++i) {
        int row0 = m0 + mw + i * 16 + r;
#pragma unroll
        for (int j = 0; j < 4; ++j) {
            int col = nw + j * 8 + 2 * q;
            *reinterpret_cast<float2*>(&P[(size_t)row0 * ODIM + col]) =
                make_float2(acc[i][j][0], acc[i][j][1]);
            *reinterpret_cast<float2*>(&P[(size_t)(row0 + 8) * ODIM + col]) =
                make_float2(acc[i][j][2], acc[i][j][3]);
        }
    }
}

// ---------------------------------------------------------------------------
// Kernel 4: out = relu(d_m*(p0+p1) + b_n). 4 float4 per thread for MLP.
// ---------------------------------------------------------------------------
__global__ __launch_bounds__(256) void combine_kernel(const float* __restrict__ bias,
                                                      float* __restrict__ out) {
    const float4* P0 = reinterpret_cast<const float4*>(g_part);
    const float4* P1 = P0 + (size_t)NROWS * ODIM / 4;
    float4* O = reinterpret_cast<float4*>(out);
    int base = blockIdx.x * 1024 + threadIdx.x;
    float4 p0[4], p1[4];
#pragma unroll
    for (int u = 0; u < 4; ++u) {
        p0[u] = P0[base + u * 256];
        p1[u] = P1[base + u * 256];
    }
#pragma unroll
    for (int u = 0; u < 4; ++u) {
        int i = base + u * 256;
        int m = i >> 5;
        int c = (i & 31) * 4;
        float4 bb = *reinterpret_cast<const float4*>(bias + c);
        float dv = g_d[m];
        float4 o;
        o.x = fmaxf(fmaf(dv, p0[u].x + p1[u].x, bb.x), 0.f);
        o.y = fmaxf(fmaf(dv, p0[u].y + p1[u].y, bb.y), 0.f);
        o.z = fmaxf(fmaf(dv, p0[u].z + p1[u].z, bb.z), 0.f);
        o.w = fmaxf(fmaf(dv, p0[u].w + p1[u].w, bb.w), 0.f);
        O[i] = o;
    }
}

// ---------------------------------------------------------------------------
extern "C" void kernel_launch(void* const* d_in, const int* in_sizes, int n_in,
                              void* d_out, int out_size) {
    const float* A = (const float*)d_in[0];
    const float* X = (const float*)d_in[1];
    const float* W = (const float*)d_in[2];
    const float* b = (const float*)d_in[3];
    float* out = (float*)d_out;
    (void)in_sizes; (void)n_in; (void)out_size;

    rowsum_kernel<<<NROWS, 256>>>(A);
    dim3 g2(NROWS / 16, 2);
    xw_kernel<<<g2, 256>>>(X, W);
    cudaFuncSetAttribute(gemm_kernel,
                         cudaFuncAttributeMaxDynamicSharedMemorySize, DYN_SMEM);
    dim3 g3(NROWS / 128, 2);
    gemm_kernel<<<g3, 256, DYN_SMEM>>>();
    combine_kernel<<<NROWS * ODIM / 4 / 1024, 256>>>(b, out);
}

// round 10
// speedup vs baseline: 1.1968x; 1.0465x over previous
#include <cuda_runtime.h>
#include <cuda_fp16.h>
#include <cstdint>

// ============================================================================
// GCN layer: out = relu(diag(d) A diag(d) X W + b), d = rsqrt(rowsum(A))
// R9: GEMM occupancy 2 CTAs/SM (RING=3, 110.6KB smem) + K-split=4 (256 CTAs).
//   k1: d = rsqrt(rowsum A); A_h = f16(A)
//   k2: Zt_h[n,k] = f16( d_k * (X@W)[k,n] )
//   k3: part[s] = A_h @ Zt_h^T  (f16 HMMA m16n8k16, K-split=4)
//   k4: out = relu(d_m*(p0+p1+p2+p3) + b)
// ============================================================================

#define NROWS 8192
#define FDIM  128
#define ODIM  128
#define KSPLIT 4

__device__ __align__(128) float  g_d[NROWS];
__device__ __align__(128) __half g_Ah[(size_t)NROWS * NROWS];            // f16(A)
__device__ __align__(128) __half g_Zth[ODIM * NROWS];                    // [n][k] f16
__device__ __align__(128) float  g_part[KSPLIT * (size_t)NROWS * ODIM];  // partials

// ---------------------------------------------------------------------------
__device__ __forceinline__ uint32_t smem_u32(const void* p) {
    uint32_t a;
    asm("{ .reg .u64 t; cvta.to.shared.u64 t, %1; cvt.u32.u64 %0, t; }"
        : "=r"(a) : "l"(p));
    return a;
}

#define CPA16(dst, src) \
    asm volatile("cp.async.cg.shared.global [%0], [%1], 16;" :: "r"(dst), "l"(src) : "memory")
#define CPA_COMMIT() asm volatile("cp.async.commit_group;" ::: "memory")
#define CPA_WAIT(n)  asm volatile("cp.async.wait_group %0;" :: "n"(n) : "memory")

__device__ __forceinline__ void mma_f16(float* c, const uint32_t* a,
                                        uint32_t b0, uint32_t b1) {
    asm volatile(
        "mma.sync.aligned.m16n8k16.row.col.f32.f16.f16.f32 "
        "{%0,%1,%2,%3}, {%4,%5,%6,%7}, {%8,%9}, {%0,%1,%2,%3};"
        : "+f"(c[0]), "+f"(c[1]), "+f"(c[2]), "+f"(c[3])
        : "r"(a[0]), "r"(a[1]), "r"(a[2]), "r"(a[3]), "r"(b0), "r"(b1));
}

__device__ __forceinline__ void ldsm_x4(uint32_t* d, uint32_t addr) {
    asm volatile("ldmatrix.sync.aligned.m8n8.x4.shared.b16 {%0,%1,%2,%3}, [%4];"
        : "=r"(d[0]), "=r"(d[1]), "=r"(d[2]), "=r"(d[3]) : "r"(addr));
}

// ---------------------------------------------------------------------------
// Kernel 1: d[r] = rsqrt(sum_k A[r,k]); g_Ah = f16(A)
// ---------------------------------------------------------------------------
__global__ __launch_bounds__(256) void rowsum_kernel(const float* __restrict__ A) {
    int row = blockIdx.x;
    const float4* p = reinterpret_cast<const float4*>(A + (size_t)row * NROWS);
    uint2* dst = reinterpret_cast<uint2*>(g_Ah + (size_t)row * NROWS);
    float s = 0.f;
#pragma unroll
    for (int i = 0; i < 8; ++i) {
        int idx = threadIdx.x + i * 256;
        float4 v = p[idx];
        s += (v.x + v.y) + (v.z + v.w);
        __half2 h0 = __floats2half2_rn(v.x, v.y);
        __half2 h1 = __floats2half2_rn(v.z, v.w);
        uint2 u;
        u.x = *reinterpret_cast<uint32_t*>(&h0);
        u.y = *reinterpret_cast<uint32_t*>(&h1);
        dst[idx] = u;
    }
#pragma unroll
    for (int o = 16; o; o >>= 1) s += __shfl_xor_sync(0xffffffffu, s, o);
    __shared__ float ws[8];
    if ((threadIdx.x & 31) == 0) ws[threadIdx.x >> 5] = s;
    __syncthreads();
    if (threadIdx.x < 8) {
        float t = ws[threadIdx.x];
        t += __shfl_xor_sync(0xffu, t, 4);
        t += __shfl_xor_sync(0xffu, t, 2);
        t += __shfl_xor_sync(0xffu, t, 1);
        if (threadIdx.x == 0) g_d[row] = rsqrtf(t);
    }
}

// ---------------------------------------------------------------------------
// Kernel 2: Zt_h[n,k] = f16_rn( d[k] * sum_f X[k,f] W[f,n] )
// ---------------------------------------------------------------------------
__global__ __launch_bounds__(256) void xw_kernel(const float* __restrict__ X,
                                                 const float* __restrict__ W) {
    __shared__ float Ws[128 * 64];
    __shared__ float Xs[16 * 128];
    int tid = threadIdx.x;
    int n0 = blockIdx.y * 64;
    int k0 = blockIdx.x * 16;
    for (int i = tid; i < 128 * 64; i += 256) {
        int f = i >> 6, nl = i & 63;
        Ws[i] = W[f * ODIM + n0 + nl];
    }
    for (int i = tid; i < 16 * 128; i += 256)
        Xs[i] = X[(size_t)(k0 + (i >> 7)) * FDIM + (i & 127)];
    __syncthreads();

    int nl = tid & 63, ks = tid >> 6;
    for (int kk = ks; kk < 16; kk += 4) {
        float acc = 0.f;
#pragma unroll 8
        for (int f = 0; f < 128; ++f) acc += Xs[kk * 128 + f] * Ws[f * 64 + nl];
        int k = k0 + kk;
        g_Zth[(size_t)(n0 + nl) * NROWS + k] = __float2half_rn(g_d[k] * acc);
    }
}

// ---------------------------------------------------------------------------
// Kernel 3: f16 GEMM. grid (64,4), 256 thr (8 warps, 64x32 warp tile).
// CTA 128x128, KT=64, RING=3, 2 CTAs/SM. ldmatrix.x4 fragments, 144B rows.
// ---------------------------------------------------------------------------
static constexpr int KT       = 64;
static constexpr int KC       = NROWS / KSPLIT;  // 2048 per K-split
static constexpr int NKT      = KC / KT;         // 32
static constexpr int ROW_B    = 144;             // 128B payload + 16B pad
static constexpr int TILE_B   = 128 * ROW_B;     // 18432 B
static constexpr int RING     = 3;
static constexpr int DYN_SMEM = 2 * RING * TILE_B;  // 110592 B -> 2 CTAs/SM

__device__ __forceinline__ void ld_tile(uint32_t Au, uint32_t Bu, int slot,
                                        int t, int m0, int kbase, int tid) {
    int k0 = kbase + t * KT;
    uint32_t Ad = Au + slot * TILE_B;
    uint32_t Bd = Bu + slot * TILE_B;
#pragma unroll
    for (int rep = 0; rep < 8; ++rep) {
        int c   = tid + rep * 256;        // 0..2047
        int isB = c >> 10;
        int rc  = c & 1023;
        int row = rc >> 3, seg = rc & 7;
        const __half* src = isB
            ? (g_Zth + (size_t)row * NROWS + k0 + seg * 8)
            : (g_Ah + (size_t)(m0 + row) * NROWS + k0 + seg * 8);
        CPA16((isB ? Bd : Ad) + (uint32_t)(row * ROW_B + seg * 16), src);
    }
}

__global__ __launch_bounds__(256, 2) void gemm_kernel() {
    extern __shared__ __align__(16) char sm[];
    uint32_t Au = smem_u32(sm);
    uint32_t Bu = Au + RING * TILE_B;

    int tid = threadIdx.x, wid = tid >> 5, lane = tid & 31;
    int m0 = blockIdx.x * 128;
    int kbase = blockIdx.y * KC;
    int mw = (wid >> 2) * 64, nw = (wid & 3) * 32;
    int r = lane >> 2, q = lane & 3;

    // ldmatrix per-lane address offsets (within a tile)
    int mi1 = (lane >> 3) & 1, mi2 = lane >> 4, rr = lane & 7;
    uint32_t aoff = (uint32_t)((mw + mi1 * 8 + rr) * ROW_B + mi2 * 16);
    uint32_t boff = (uint32_t)((nw + mi2 * 8 + rr) * ROW_B + mi1 * 16);

    float acc[4][4][4];
#pragma unroll
    for (int i = 0; i < 4; ++i)
#pragma unroll
        for (int j = 0; j < 4; ++j)
#pragma unroll
            for (int v = 0; v < 4; ++v) acc[i][j][v] = 0.f;

    // prologue: tiles 0..RING-2 in flight
#pragma unroll
    for (int s = 0; s < RING - 1; ++s) {
        ld_tile(Au, Bu, s, s, m0, kbase, tid);
        CPA_COMMIT();
    }
    CPA_WAIT(RING - 2);      // tile 0 complete
    __syncthreads();

    uint32_t fa[2][4][4], fb[2][2][4];

    for (int t = 0; t < NKT; ++t) {
        if (t + RING - 1 < NKT)
            ld_tile(Au, Bu, (t + RING - 1) % RING, t + RING - 1, m0, kbase, tid);
        CPA_COMMIT();

        uint32_t At = Au + (t % RING) * TILE_B;
        uint32_t Bt = Bu + (t % RING) * TILE_B;

        // preload ks=0 fragments
#pragma unroll
        for (int i = 0; i < 4; ++i)
            ldsm_x4(fa[0][i], At + aoff + (uint32_t)(i * 16 * ROW_B));
        ldsm_x4(fb[0][0], Bt + boff);
        ldsm_x4(fb[0][1], Bt + boff + (uint32_t)(16 * ROW_B));

#pragma unroll
        for (int ks = 0; ks < 4; ++ks) {
            int cur = ks & 1;
            if (ks < 3) {
                uint32_t ko = (uint32_t)((ks + 1) * 32);
#pragma unroll
                for (int i = 0; i < 4; ++i)
                    ldsm_x4(fa[cur ^ 1][i], At + aoff + ko + (uint32_t)(i * 16 * ROW_B));
                ldsm_x4(fb[cur ^ 1][0], Bt + boff + ko);
                ldsm_x4(fb[cur ^ 1][1], Bt + boff + ko + (uint32_t)(16 * ROW_B));
            }
#pragma unroll
            for (int i = 0; i < 4; ++i) {
                mma_f16(acc[i][0], fa[cur][i], fb[cur][0][0], fb[cur][0][1]);
                mma_f16(acc[i][1], fa[cur][i], fb[cur][0][2], fb[cur][0][3]);
                mma_f16(acc[i][2], fa[cur][i], fb[cur][1][0], fb[cur][1][1]);
                mma_f16(acc[i][3], fa[cur][i], fb[cur][1][2], fb[cur][1][3]);
            }
        }

        CPA_WAIT(RING - 2);  // next tile (t+1) complete
        __syncthreads();
    }

    // write K-split partials
    float* P = g_part + (size_t)blockIdx.y * NROWS * ODIM;
#pragma unroll
    for (int i = 0; i < 4; ++i) {
        int row0 = m0 + mw + i * 16 + r;
#pragma unroll
        for (int j = 0; j < 4; ++j) {
            int col = nw + j * 8 + 2 * q;
            *reinterpret_cast<float2*>(&P[(size_t)row0 * ODIM + col]) =
                make_float2(acc[i][j][0], acc[i][j][1]);
            *reinterpret_cast<float2*>(&P[(size_t)(row0 + 8) * ODIM + col]) =
                make_float2(acc[i][j][2], acc[i][j][3]);
        }
    }
}

// ---------------------------------------------------------------------------
// Kernel 4: out = relu(d_m * sum_s p_s + b_n). 4 float4 per thread.
// ---------------------------------------------------------------------------
__global__ __launch_bounds__(256) void combine_kernel(const float* __restrict__ bias,
                                                      float* __restrict__ out) {
    const float4* P = reinterpret_cast<const float4*>(g_part);
    const size_t QT = (size_t)NROWS * ODIM / 4;
    float4* O = reinterpret_cast<float4*>(out);
    int base = blockIdx.x * 1024 + threadIdx.x;
#pragma unroll
    for (int u = 0; u < 4; ++u) {
        int i = base + u * 256;
        float4 p0 = P[i];
        float4 p1 = P[i + QT];
        float4 p2 = P[i + 2 * QT];
        float4 p3 = P[i + 3 * QT];
        float sx = (p0.x + p1.x) + (p2.x + p3.x);
        float sy = (p0.y + p1.y) + (p2.y + p3.y);
        float sz = (p0.z + p1.z) + (p2.z + p3.z);
        float sw = (p0.w + p1.w) + (p2.w + p3.w);
        int m = i >> 5;
        int c = (i & 31) * 4;
        float4 bb = *reinterpret_cast<const float4*>(bias + c);
        float dv = g_d[m];
        float4 o;
        o.x = fmaxf(fmaf(dv, sx, bb.x), 0.f);
        o.y = fmaxf(fmaf(dv, sy, bb.y), 0.f);
        o.z = fmaxf(fmaf(dv, sz, bb.z), 0.f);
        o.w = fmaxf(fmaf(dv, sw, bb.w), 0.f);
        O[i] = o;
    }
}

// ---------------------------------------------------------------------------
extern "C" void kernel_launch(void* const* d_in, const int* in_sizes, int n_in,
                              void* d_out, int out_size) {
    const float* A = (const float*)d_in[0];
    const float* X = (const float*)d_in[1];
    const float* W = (const float*)d_in[2];
    const float* b = (const float*)d_in[3];
    float* out = (float*)d_out;
    (void)in_sizes; (void)n_in; (void)out_size;

    rowsum_kernel<<<NROWS, 256>>>(A);
    dim3 g2(NROWS / 16, 2);
    xw_kernel<<<g2, 256>>>(X, W);
    cudaFuncSetAttribute(gemm_kernel,
                         cudaFuncAttributeMaxDynamicSharedMemorySize, DYN_SMEM);
    dim3 g3(NROWS / 128, KSPLIT);
    gemm_kernel<<<g3, 256, DYN_SMEM>>>();
    combine_kernel<<<NROWS * ODIM / 4 / 1024, 256>>>(b, out);
}